// round 11
// baseline (speedup 1.0000x reference)
#include <cuda_runtime.h>
#include <cuda_bf16.h>
#include <cstdint>

// GANLoss: out = -mean(prob[n, targets[n]] * reward[n]), N=8192, C=32000.
// Full-overlap PDL (entry trigger) + per-CTA flag/payload handshake:
// each gather CTA fire-and-forgets ONE st.release.gpu.u64 packing
// {flag=1, partial-float-bits}; the resident finalize warp acquire-spins on
// 32 distinct words in parallel (no same-address RMW serialization),
// fixed-order reduces (rel_err 0), writes out, resets words for replay.

#define NBLOCKS  32
#define NTHREADS 256

__device__ unsigned long long g_slots[NBLOCKS];   // zero-initialized

__global__ __launch_bounds__(NTHREADS) void gather_kernel(
    const float* __restrict__ prob,
    const int* __restrict__ targets,
    const float* __restrict__ reward,
    int N, long long C)
{
    // Release the dependent finalize grid immediately; data visibility is
    // handled by the release/acquire slot protocol below.
    cudaTriggerProgrammaticLaunchCompletion();

    int idx = blockIdx.x * blockDim.x + threadIdx.x;

    float v = 0.0f;
    if (idx < N) {
        int t = targets[idx];
        v = __ldg(&prob[(long long)idx * C + (long long)t]) * __ldg(&reward[idx]);
    }

    // warp reduce (5 shuffles)
    #pragma unroll
    for (int off = 16; off > 0; off >>= 1)
        v += __shfl_xor_sync(0xFFFFFFFFu, v, off);

    __shared__ float s_warp[NTHREADS / 32];
    const int lane = threadIdx.x & 31;
    const int wid  = threadIdx.x >> 5;
    if (lane == 0) s_warp[wid] = v;
    __syncthreads();

    if (threadIdx.x < 32) {
        float w = (lane < NTHREADS / 32) ? s_warp[lane] : 0.0f;
        #pragma unroll
        for (int off = 4; off > 0; off >>= 1)
            w += __shfl_xor_sync(0xFFFFFFFFu, w, off);
        if (lane == 0) {
            unsigned long long word =
                (1ULL << 63) | (unsigned long long)__float_as_uint(w);
            // single fire-and-forget release store: flag + payload together
            asm volatile("st.release.gpu.u64 [%0], %1;"
                         :: "l"(&g_slots[blockIdx.x]), "l"(word) : "memory");
        }
    }
}

__global__ __launch_bounds__(32) void finalize_kernel(
    float* __restrict__ out, float neg_inv_n)
{
    const int lane = threadIdx.x;

    // Each lane spins on its own slot (32 independent addresses).
    unsigned long long word;
    do {
        asm volatile("ld.acquire.gpu.u64 %0, [%1];"
                     : "=l"(word) : "l"(&g_slots[lane]) : "memory");
    } while (!(word >> 63));

    float v = __uint_as_float((unsigned int)word);

    #pragma unroll
    for (int off = 16; off > 0; off >>= 1)
        v += __shfl_xor_sync(0xFFFFFFFFu, v, off);

    if (lane == 0)
        out[0] = v * neg_inv_n;

    // reset slots for the next graph replay (stream-order visible)
    g_slots[lane] = 0ULL;
}

extern "C" void kernel_launch(void* const* d_in, const int* in_sizes, int n_in,
                              void* d_out, int out_size)
{
    const float* prob    = (const float*)d_in[0];
    const int*   targets = (const int*)d_in[1];
    const float* reward  = (const float*)d_in[2];
    float*       out     = (float*)d_out;

    const int N = in_sizes[2];                       // 8192
    const long long C = (long long)in_sizes[0] / N;  // 32000

    gather_kernel<<<NBLOCKS, NTHREADS>>>(prob, targets, reward, N, C);

    cudaLaunchConfig_t cfg = {};
    cfg.gridDim  = dim3(1, 1, 1);
    cfg.blockDim = dim3(32, 1, 1);
    cfg.dynamicSmemBytes = 0;
    cfg.stream = 0;
    cudaLaunchAttribute attr;
    attr.id = cudaLaunchAttributeProgrammaticStreamSerialization;
    attr.val.programmaticStreamSerializationAllowed = 1;
    cfg.attrs = &attr;
    cfg.numAttrs = 1;

    float neg_inv_n = -1.0f / (float)N;
    cudaLaunchKernelEx(&cfg, finalize_kernel, out, neg_inv_n);
}

// round 12
// speedup vs baseline: 1.0433x; 1.0433x over previous
#include <cuda_runtime.h>
#include <cuda_bf16.h>

// GANLoss: out = -mean(prob[n, targets[n]] * reward[n]), N=8192, C=32000.
// SINGLE kernel node. Each of 32 co-resident CTAs block-reduces and issues
// one fire-and-forget st.release.gpu.u64 {flag|payload} into its slot.
// Block 0's warp 0 acquire-spins on the 32 slots (per-lane), fixed-order
// reduces (rel_err 0), writes out, and resets slots for graph replay.
// No membars, no RMWs, no second launch.

#define NBLOCKS  32
#define NTHREADS 256

__device__ unsigned long long g_slots[NBLOCKS];   // zero-initialized

__global__ __launch_bounds__(NTHREADS) void ganloss_kernel(
    const float* __restrict__ prob,
    const int* __restrict__ targets,
    const float* __restrict__ reward,
    float* __restrict__ out,
    int N, long long C, float neg_inv_n)
{
    const int idx  = blockIdx.x * blockDim.x + threadIdx.x;
    const int lane = threadIdx.x & 31;
    const int wid  = threadIdx.x >> 5;

    float v = 0.0f;
    if (idx < N) {
        int t = targets[idx];
        v = __ldg(&prob[(long long)idx * C + (long long)t]) * __ldg(&reward[idx]);
    }

    // warp reduce (5 shuffles)
    #pragma unroll
    for (int off = 16; off > 0; off >>= 1)
        v += __shfl_xor_sync(0xFFFFFFFFu, v, off);

    __shared__ float s_warp[NTHREADS / 32];
    if (lane == 0) s_warp[wid] = v;
    __syncthreads();

    if (threadIdx.x < 32) {
        float w = (lane < NTHREADS / 32) ? s_warp[lane] : 0.0f;
        #pragma unroll
        for (int off = 4; off > 0; off >>= 1)
            w += __shfl_xor_sync(0xFFFFFFFFu, w, off);
        if (lane == 0) {
            unsigned long long word =
                (1ULL << 63) | (unsigned long long)__float_as_uint(w);
            // fire-and-forget release store: flag + payload in one word
            asm volatile("st.release.gpu.u64 [%0], %1;"
                         :: "l"(&g_slots[blockIdx.x]), "l"(word) : "memory");
        }
    }

    // Block 0, warp 0: dedicated consumer. All 32 CTAs are co-resident
    // (32 <= 148 SMs), so spinning here cannot deadlock.
    if (blockIdx.x == 0 && threadIdx.x < 32) {
        unsigned long long word;
        do {
            asm volatile("ld.acquire.gpu.u64 %0, [%1];"
                         : "=l"(word) : "l"(&g_slots[lane]) : "memory");
        } while (!(word >> 63));

        float p = __uint_as_float((unsigned int)word);
        #pragma unroll
        for (int off = 16; off > 0; off >>= 1)
            p += __shfl_xor_sync(0xFFFFFFFFu, p, off);

        if (lane == 0)
            out[0] = p * neg_inv_n;

        // reset for the next graph replay (kernel-boundary visibility)
        g_slots[lane] = 0ULL;
    }
}

extern "C" void kernel_launch(void* const* d_in, const int* in_sizes, int n_in,
                              void* d_out, int out_size)
{
    const float* prob    = (const float*)d_in[0];
    const int*   targets = (const int*)d_in[1];
    const float* reward  = (const float*)d_in[2];
    float*       out     = (float*)d_out;

    const int N = in_sizes[2];                       // 8192
    const long long C = (long long)in_sizes[0] / N;  // 32000

    ganloss_kernel<<<NBLOCKS, NTHREADS>>>(prob, targets, reward, out,
                                          N, C, -1.0f / (float)N);
}

// round 13
// speedup vs baseline: 1.0483x; 1.0048x over previous
#include <cuda_runtime.h>
#include <cuda_bf16.h>

// GANLoss: out = -mean(prob[n, targets[n]] * reward[n]), N=8192, C=32000.
// SINGLE kernel node, dedicated consumer block:
//   block 0:      no gather work; warp 0 acquire-spins on 32 slots from t=0.
//   blocks 1..32: gather 256 rows each, block-reduce, ONE fire-and-forget
//                 st.release.gpu.u64 {flag|payload} into slot[blockIdx-1].
// Consumer fixed-order reduces (rel_err 0), writes out, resets slots.
// 33 CTAs co-resident on 148 SMs -> spin cannot deadlock.
// 32-bit gather indexing: N*C = 262.1M < 2^31.

#define NPRODUCERS 32
#define NTHREADS   256

__device__ unsigned long long g_slots[NPRODUCERS];   // zero-initialized

__global__ __launch_bounds__(NTHREADS) void ganloss_kernel(
    const float* __restrict__ prob,
    const int* __restrict__ targets,
    const float* __restrict__ reward,
    float* __restrict__ out,
    int N, unsigned int C, float neg_inv_n)
{
    const int lane = threadIdx.x & 31;

    if (blockIdx.x == 0) {
        // ---- dedicated consumer: spinning from launch ----
        if (threadIdx.x < 32) {
            unsigned long long word;
            do {
                asm volatile("ld.acquire.gpu.u64 %0, [%1];"
                             : "=l"(word) : "l"(&g_slots[lane]) : "memory");
            } while (!(word >> 63));

            float p = __uint_as_float((unsigned int)word);
            #pragma unroll
            for (int off = 16; off > 0; off >>= 1)
                p += __shfl_xor_sync(0xFFFFFFFFu, p, off);

            if (lane == 0)
                out[0] = p * neg_inv_n;

            // reset for the next graph replay (kernel-boundary visibility)
            g_slots[lane] = 0ULL;
        }
        return;
    }

    // ---- producers: blocks 1..32 ----
    const int idx = (blockIdx.x - 1) * NTHREADS + threadIdx.x;
    const int wid = threadIdx.x >> 5;

    float v = 0.0f;
    if (idx < N) {
        unsigned int t = (unsigned int)targets[idx];
        unsigned int off32 = (unsigned int)idx * C + t;   // < 2^31
        v = __ldg(&prob[off32]) * __ldg(&reward[idx]);
    }

    // warp reduce (5 shuffles)
    #pragma unroll
    for (int off = 16; off > 0; off >>= 1)
        v += __shfl_xor_sync(0xFFFFFFFFu, v, off);

    __shared__ float s_warp[NTHREADS / 32];
    if (lane == 0) s_warp[wid] = v;
    __syncthreads();

    if (threadIdx.x < 32) {
        float w = (lane < NTHREADS / 32) ? s_warp[lane] : 0.0f;
        #pragma unroll
        for (int off = 4; off > 0; off >>= 1)
            w += __shfl_xor_sync(0xFFFFFFFFu, w, off);
        if (lane == 0) {
            unsigned long long word =
                (1ULL << 63) | (unsigned long long)__float_as_uint(w);
            asm volatile("st.release.gpu.u64 [%0], %1;"
                         :: "l"(&g_slots[blockIdx.x - 1]), "l"(word) : "memory");
        }
    }
}

extern "C" void kernel_launch(void* const* d_in, const int* in_sizes, int n_in,
                              void* d_out, int out_size)
{
    const float* prob    = (const float*)d_in[0];
    const int*   targets = (const int*)d_in[1];
    const float* reward  = (const float*)d_in[2];
    float*       out     = (float*)d_out;

    const int N = in_sizes[2];                             // 8192
    const unsigned int C = (unsigned int)(in_sizes[0] / N); // 32000

    ganloss_kernel<<<NPRODUCERS + 1, NTHREADS>>>(prob, targets, reward, out,
                                                 N, C, -1.0f / (float)N);
}